// round 15
// baseline (speedup 1.0000x reference)
#include <cuda_runtime.h>
#include <cstdint>

// WeightedEmbeddingBag: B=4096, N=200, M=26, VOCAB=100000, D=128
//   d_in[0] input   int32 [B,N]   d_in[1] weights fp32 [B,N]
//   d_in[2] offsets int32 [B,M]   d_in[3] emb     fp32 [VOCAB,D]
// Output fp32 [B,M,D].
//
// Warp-per-batch running accumulator with snapshots at offset boundaries
// (identical numerics to the reference cumsum-difference).
//
// Roofline status: ~93% of the achievable LTS cap (~510MB L2 bytes / 75K cyc
// vs ~6300 B/cyc HW cap; ncu L2=47.2% ~= achievable fraction of theoretical).
// Mandatory bytes 484MB -> floor ~37-39us. Structural splits all regressed;
// eviction-policy levers neutral. R15 (final lever): ids/weights preload via
// __ldcs (evict-first, one-shot stream) + policy-hinted evict-last gathers +
// __stcs output.

#define BB 4096
#define NN 200
#define MM 26
#define WARPS_PER_CTA 4
#define UNROLL 8

// Table gather: 16B per lane, L2 evict-last via cache-hint policy.
__device__ __forceinline__ float4 ld_evict_last(const void* p, uint64_t pol) {
    float4 r;
    asm("ld.global.L2::cache_hint.v4.f32 {%0,%1,%2,%3}, [%4], %5;"
        : "=f"(r.x), "=f"(r.y), "=f"(r.z), "=f"(r.w)
        : "l"(p), "l"(pol));
    return r;
}

__global__ __launch_bounds__(32 * WARPS_PER_CTA)
void ebag_kernel(const int*   __restrict__ input,
                 const float* __restrict__ psw,
                 const int*   __restrict__ offsets,
                 const char*  __restrict__ emb_bytes,  // emb as bytes, row=512B
                 float4*      __restrict__ out4)       // [B, M, 32] float4
{
    const int wid  = threadIdx.x >> 5;
    const int lane = threadIdx.x & 31;
    const int b    = blockIdx.x * WARPS_PER_CTA + wid;
    if (b >= BB) return;

    __shared__ int   s_id[WARPS_PER_CTA][NN];
    __shared__ float s_w [WARPS_PER_CTA][NN];
    __shared__ int   s_off[WARPS_PER_CTA][32];

    const int*   in_b = input + (size_t)b * NN;
    const float* w_b  = psw   + (size_t)b * NN;

    // Coalesced one-time preload (streaming: one-shot data, evict-first so it
    // never displaces table lines in L2).
    #pragma unroll
    for (int n = lane; n < NN; n += 32) {
        s_id[wid][n] = __ldcs(&in_b[n]);
        s_w [wid][n] = __ldcs(&w_b[n]);
    }
    if (lane < MM)
        s_off[wid][lane] = __ldcs(&offsets[(size_t)b * MM + lane]);
    __syncwarp();

    // L2 access policy: evict-last for the full fraction (hoisted, 1 op).
    uint64_t pol;
    asm("createpolicy.fractional.L2::evict_last.b64 %0, 1.0;" : "=l"(pol));

    // Per-lane base: lane's 16B slice within each 512B embedding row.
    const char* emb_lane = emb_bytes + (unsigned)(lane << 4);
    float4*     o_b      = out4 + (size_t)b * MM * 32;

    int nmax = s_off[wid][MM - 1];
    if (nmax > NN - 1) nmax = NN - 1;   // defensive: fail clean, never fault
    if (nmax < 0)      nmax = 0;

    float4 acc  = make_float4(0.f, 0.f, 0.f, 0.f);
    float4 snap = make_float4(0.f, 0.f, 0.f, 0.f);
    int m   = 0;
    int cur = s_off[wid][0];

    for (int n0 = 0; n0 <= nmax; n0 += UNROLL) {
        // UNROLL independent 512B gathers in flight (tail clamps to nmax;
        // duplicate loads are discarded by the j-loop guard). 32-bit offset:
        // id < 100000 -> id<<9 < 2^26.
        float4 v[UNROLL];
        #pragma unroll
        for (int j = 0; j < UNROLL; j++) {
            int n  = n0 + j;
            int nc = (n <= nmax) ? n : nmax;
            const unsigned off = (unsigned)s_id[wid][nc] << 9;
            v[j] = ld_evict_last(emb_lane + off, pol);
        }

        #pragma unroll
        for (int j = 0; j < UNROLL; j++) {
            const int n = n0 + j;
            if (n <= nmax) {
                const float w = s_w[wid][n];
                acc.x = fmaf(w, v[j].x, acc.x);
                acc.y = fmaf(w, v[j].y, acc.y);
                acc.z = fmaf(w, v[j].z, acc.z);
                acc.w = fmaf(w, v[j].w, acc.w);

                // Emit every segment ending at n (duplicate offsets -> empty
                // segments -> exact zeros, matching the reference).
                while (cur == n) {
                    float4 r = make_float4(acc.x - snap.x, acc.y - snap.y,
                                           acc.z - snap.z, acc.w - snap.w);
                    __stcs(&o_b[m * 32 + lane], r);   // streaming: evict-first
                    snap = acc;
                    m++;
                    cur = (m < MM) ? s_off[wid][m] : NN;  // NN never matches
                }
            }
        }
    }
}

extern "C" void kernel_launch(void* const* d_in, const int* in_sizes, int n_in,
                              void* d_out, int out_size)
{
    const int*   input   = (const int*)  d_in[0];
    const float* psw     = (const float*)d_in[1];
    const int*   offsets = (const int*)  d_in[2];
    const char*  emb     = (const char*) d_in[3];
    float4*      out4    = (float4*)d_out;

    dim3 grid(BB / WARPS_PER_CTA);
    dim3 block(32 * WARPS_PER_CTA);
    ebag_kernel<<<grid, block>>>(input, psw, offsets, emb, out4);
}